// round 7
// baseline (speedup 1.0000x reference)
#include <cuda_runtime.h>
#include <math.h>
#include <stdint.h>

// Problem constants
#define BB   2
#define TT   2048
#define CC   1024
#define NH   16
#define HD   64
#define BT   (BB * TT)        // 4096
#define KQV3 (3 * CC)         // 3072

// Scratch (allocation-free rule: __device__ globals)
__device__ float g_kqv[(size_t)BT * KQV3];   // qkv activations (tf32-rounded)
__device__ float g_y[(size_t)BT * CC];       // attention out (tf32-rounded)
__device__ float g_xtf[(size_t)BT * CC];     // x, tf32-rounded
__device__ float g_wk[(size_t)KQV3 * CC];    // W_kqv, tf32-rounded
__device__ float g_wp[(size_t)CC * CC];      // W_proj, tf32-rounded

// ---------------------------------------------------------------------------
// Helpers
// ---------------------------------------------------------------------------
__device__ __forceinline__ uint32_t f2tf32(float x) {
    uint32_t r;
    asm("cvt.rna.tf32.f32 %0, %1;" : "=r"(r) : "f"(x));
    return r;
}

__device__ __forceinline__ void mma_tf32(float* c, const uint32_t* a,
                                         uint32_t b0, uint32_t b1) {
    asm volatile(
        "mma.sync.aligned.m16n8k8.row.col.f32.tf32.tf32.f32 "
        "{%0,%1,%2,%3}, {%4,%5,%6,%7}, {%8,%9}, {%0,%1,%2,%3};\n"
        : "+f"(c[0]), "+f"(c[1]), "+f"(c[2]), "+f"(c[3])
        : "r"(a[0]), "r"(a[1]), "r"(a[2]), "r"(a[3]), "r"(b0), "r"(b1));
}

__device__ __forceinline__ void cpa16(uint32_t saddr, const void* gptr) {
    asm volatile("cp.async.cg.shared.global [%0], [%1], 16;" :: "r"(saddr), "l"(gptr));
}
__device__ __forceinline__ void cpcommit() {
    asm volatile("cp.async.commit_group;" ::: "memory");
}
template <int N>
__device__ __forceinline__ void cpwait() {
    asm volatile("cp.async.wait_group %0;" :: "n"(N) : "memory");
}

// ---------------------------------------------------------------------------
// Pre-pass: tf32-round an fp32 array (vectorized).
// ---------------------------------------------------------------------------
__global__ __launch_bounds__(256)
void cvt_tf32_kernel(const float4* __restrict__ src, uint4* __restrict__ dst,
                     int n4) {
    const int i = blockIdx.x * blockDim.x + threadIdx.x;
    if (i < n4) {
        float4 v = src[i];
        uint4 o;
        o.x = f2tf32(v.x); o.y = f2tf32(v.y);
        o.z = f2tf32(v.z); o.w = f2tf32(v.w);
        dst[i] = o;
    }
}

// ---------------------------------------------------------------------------
// tf32 tensor-core GEMM, 3-stage cp.async pipeline. Inputs are PRE-ROUNDED
// tf32 bit patterns -> raw fragment loads, no cvt in mainloop.
// C[m,n] = sum_k A[m,k]*W[n,k] + bias[n].  BM=BN=128, BK=16. 256 thr, 8 warps
// (2m x 4n), warp tile 64x32. smem [row][k] stride 20 (conflict-free frags).
// EPI_CVT: tf32-round the epilogue output (for tensors feeding later mmas).
// ---------------------------------------------------------------------------
#define GPAD     20
#define GTILEW   (128 * GPAD)          // 2560 words / tile
#define GSTAGEW  (2 * GTILEW)          // 5120 words / stage (A+W)
#define GSTAGES  3
#define GSMEM_BYTES (GSTAGES * GSTAGEW * 4)   // 61440

template <bool EPI_CVT>
__global__ __launch_bounds__(256)
void gemm_tf32(const float* __restrict__ A, const float* __restrict__ W,
               const float* __restrict__ bias, float* __restrict__ Cmat,
               int M, int N, int K) {
    extern __shared__ uint32_t gsm[];

    const int tid  = threadIdx.x;
    const int lane = tid & 31;
    const int wid  = tid >> 5;
    const int g    = lane >> 2;
    const int q    = lane & 3;
    const int wm   = wid >> 2;
    const int wn   = wid & 3;

    const int m0 = blockIdx.y * 128;
    const int n0 = blockIdx.x * 128;
    const float* Abase = A + (size_t)m0 * K;
    const float* Wbase = W + (size_t)n0 * K;
    const int niter = K >> 4;

    const int r0  = tid >> 2,          k40 = (tid & 3) << 2;
    const int r1  = (tid + 256) >> 2,  k41 = ((tid + 256) & 3) << 2;

    float acc[4][4][4];
    #pragma unroll
    for (int mi = 0; mi < 4; mi++)
        #pragma unroll
        for (int ni = 0; ni < 4; ni++)
            #pragma unroll
            for (int r = 0; r < 4; r++) acc[mi][ni][r] = 0.0f;

    #pragma unroll
    for (int p = 0; p < GSTAGES - 1; p++) {
        if (p < niter) {
            const int kb = p << 4;
            uint32_t sb = (uint32_t)__cvta_generic_to_shared(gsm + p * GSTAGEW);
            cpa16(sb + (r0 * GPAD + k40) * 4, Abase + (size_t)r0 * K + kb + k40);
            cpa16(sb + (r1 * GPAD + k41) * 4, Abase + (size_t)r1 * K + kb + k41);
            uint32_t wb = sb + GTILEW * 4;
            cpa16(wb + (r0 * GPAD + k40) * 4, Wbase + (size_t)r0 * K + kb + k40);
            cpa16(wb + (r1 * GPAD + k41) * 4, Wbase + (size_t)r1 * K + kb + k41);
        }
        cpcommit();
    }

    for (int i = 0; i < niter; i++) {
        if (i + 2 < niter) {
            const int ii = i + 2;
            const int kb = ii << 4;
            uint32_t sb = (uint32_t)__cvta_generic_to_shared(
                gsm + (ii % GSTAGES) * GSTAGEW);
            cpa16(sb + (r0 * GPAD + k40) * 4, Abase + (size_t)r0 * K + kb + k40);
            cpa16(sb + (r1 * GPAD + k41) * 4, Abase + (size_t)r1 * K + kb + k41);
            uint32_t wb = sb + GTILEW * 4;
            cpa16(wb + (r0 * GPAD + k40) * 4, Wbase + (size_t)r0 * K + kb + k40);
            cpa16(wb + (r1 * GPAD + k41) * 4, Wbase + (size_t)r1 * K + kb + k41);
        }
        cpcommit();
        cpwait<GSTAGES - 1>();
        __syncthreads();

        const uint32_t* sa = gsm + (i % GSTAGES) * GSTAGEW;
        const uint32_t* sw = sa + GTILEW;

        #pragma unroll
        for (int ks = 0; ks < 16; ks += 8) {
            uint32_t af[4][4];
            uint32_t bf[4][2];
            #pragma unroll
            for (int mi = 0; mi < 4; mi++) {
                const int m = wm * 64 + mi * 16;
                af[mi][0] = sa[(m + g) * GPAD + ks + q];
                af[mi][1] = sa[(m + g + 8) * GPAD + ks + q];
                af[mi][2] = sa[(m + g) * GPAD + ks + q + 4];
                af[mi][3] = sa[(m + g + 8) * GPAD + ks + q + 4];
            }
            #pragma unroll
            for (int ni = 0; ni < 4; ni++) {
                const int n = wn * 32 + ni * 8;
                bf[ni][0] = sw[(n + g) * GPAD + ks + q];
                bf[ni][1] = sw[(n + g) * GPAD + ks + q + 4];
            }
            #pragma unroll
            for (int mi = 0; mi < 4; mi++)
                #pragma unroll
                for (int ni = 0; ni < 4; ni++)
                    mma_tf32(acc[mi][ni], af[mi], bf[ni][0], bf[ni][1]);
        }
        __syncthreads();
    }

    #pragma unroll
    for (int mi = 0; mi < 4; mi++) {
        const int m = m0 + wm * 64 + mi * 16 + g;
        #pragma unroll
        for (int ni = 0; ni < 4; ni++) {
            const int n = n0 + wn * 32 + ni * 8 + 2 * q;
            const float b0 = __ldg(&bias[n]);
            const float b1 = __ldg(&bias[n + 1]);
            float o00 = acc[mi][ni][0] + b0, o01 = acc[mi][ni][1] + b1;
            float o10 = acc[mi][ni][2] + b0, o11 = acc[mi][ni][3] + b1;
            if (EPI_CVT) {
                o00 = __uint_as_float(f2tf32(o00));
                o01 = __uint_as_float(f2tf32(o01));
                o10 = __uint_as_float(f2tf32(o10));
                o11 = __uint_as_float(f2tf32(o11));
            }
            *reinterpret_cast<float2*>(&Cmat[(size_t)m * N + n]) =
                make_float2(o00, o01);
            *reinterpret_cast<float2*>(&Cmat[(size_t)(m + 8) * N + n]) =
                make_float2(o10, o11);
        }
    }
}

// ---------------------------------------------------------------------------
// Flash attention, tf32 mma, cp.async double-buffered K/V.
// kqv is PRE-ROUNDED tf32 -> raw fragment loads. Only P stores convert.
// Grid (T/64, NH, B), 128 threads (4 warps), warp owns 16 q-rows.
// sQ [row][hd] stride 68 (reused as sP); sK,sV [key][hd] stride 72, 2 stages.
// ---------------------------------------------------------------------------
#define QP_ST 68
#define KV_ST 72
#define QW  (64 * QP_ST)
#define KVW (64 * KV_ST)
#define ASTW (2 * KVW)
#define ATT_BYTES ((QW + 2 * ASTW) * 4)   // 91136

__global__ __launch_bounds__(128)
void attn_tc_kernel(const float* __restrict__ kqv, float* __restrict__ y) {
    extern __shared__ uint32_t smem[];
    uint32_t* sQ = smem;

    const int qb  = blockIdx.x;
    const int h   = blockIdx.y;
    const int b   = blockIdx.z;
    const int tid = threadIdx.x;
    const int w   = tid >> 5;
    const int lane = tid & 31;
    const int g   = lane >> 2;
    const int q   = lane & 3;
    const int q0  = qb * 64;
    const int mrow = 16 * w;
    const float scale = 0.125f;

    const size_t tokStride = (size_t)NH * 3 * HD;
    const size_t headOff   = (size_t)h * 3 * HD;

    auto issueKV = [&](int kb) {
        const int k0 = kb * 64;
        uint32_t base = (uint32_t)__cvta_generic_to_shared(
            smem + QW + (kb & 1) * ASTW);
        #pragma unroll
        for (int j = 0; j < 8; j++) {
            const int c   = tid + j * 128;
            const int row = c >> 4;
            const int c4  = (c & 15) << 2;
            const float* gk =
                &kqv[((size_t)(b * TT + k0 + row)) * tokStride + headOff + c4];
            cpa16(base + (row * KV_ST + c4) * 4, gk);                 // K
            cpa16(base + (KVW + row * KV_ST + c4) * 4, gk + 2 * HD);  // V
        }
    };

    issueKV(0);
    cpcommit();

    for (int idx = tid; idx < 64 * 16; idx += 128) {
        const int row = idx >> 4;
        const int c4  = (idx & 15) << 2;
        uint4 v = *reinterpret_cast<const uint4*>(
            &kqv[((size_t)(b * TT + q0 + row)) * tokStride + headOff + HD + c4]);
        uint32_t* dst = &sQ[row * QP_ST + c4];
        dst[0] = v.x; dst[1] = v.y; dst[2] = v.z; dst[3] = v.w;
    }
    __syncthreads();

    uint32_t qf[8][4];
    #pragma unroll
    for (int ks = 0; ks < 8; ks++) {
        qf[ks][0] = sQ[(mrow + g) * QP_ST + ks * 8 + q];
        qf[ks][1] = sQ[(mrow + g + 8) * QP_ST + ks * 8 + q];
        qf[ks][2] = sQ[(mrow + g) * QP_ST + ks * 8 + q + 4];
        qf[ks][3] = sQ[(mrow + g + 8) * QP_ST + ks * 8 + q + 4];
    }

    float oacc[8][4];
    #pragma unroll
    for (int ni = 0; ni < 8; ni++)
        #pragma unroll
        for (int r = 0; r < 4; r++) oacc[ni][r] = 0.0f;
    float m_0 = -1e30f, m_1 = -1e30f, l_0 = 0.0f, l_1 = 0.0f;

    const int qrow0 = q0 + mrow + g;
    const int qrow1 = qrow0 + 8;

    for (int kb = 0; kb <= qb; kb++) {
        const int k0 = kb * 64;
        if (kb + 1 <= qb) issueKV(kb + 1);
        cpcommit();
        cpwait<1>();
        __syncthreads();

        const uint32_t* sK = smem + QW + (kb & 1) * ASTW;
        const uint32_t* sV = sK + KVW;

        float sa[8][4];
        #pragma unroll
        for (int ni = 0; ni < 8; ni++)
            #pragma unroll
            for (int r = 0; r < 4; r++) sa[ni][r] = 0.0f;

        #pragma unroll
        for (int ks = 0; ks < 8; ks++) {
            #pragma unroll
            for (int ni = 0; ni < 8; ni++) {
                uint32_t b0 = sK[(ni * 8 + g) * KV_ST + ks * 8 + q];
                uint32_t b1 = sK[(ni * 8 + g) * KV_ST + ks * 8 + q + 4];
                mma_tf32(sa[ni], qf[ks], b0, b1);
            }
        }

        const bool diag = (kb == qb);
        #pragma unroll
        for (int ni = 0; ni < 8; ni++) {
            const int key = k0 + ni * 8 + 2 * q;
            sa[ni][0] = (diag && key     > qrow0) ? -1e30f : sa[ni][0] * scale;
            sa[ni][1] = (diag && key + 1 > qrow0) ? -1e30f : sa[ni][1] * scale;
            sa[ni][2] = (diag && key     > qrow1) ? -1e30f : sa[ni][2] * scale;
            sa[ni][3] = (diag && key + 1 > qrow1) ? -1e30f : sa[ni][3] * scale;
        }

        float mx0 = -1e30f, mx1 = -1e30f;
        #pragma unroll
        for (int ni = 0; ni < 8; ni++) {
            mx0 = fmaxf(mx0, fmaxf(sa[ni][0], sa[ni][1]));
            mx1 = fmaxf(mx1, fmaxf(sa[ni][2], sa[ni][3]));
        }
        mx0 = fmaxf(mx0, __shfl_xor_sync(0xffffffffu, mx0, 1));
        mx0 = fmaxf(mx0, __shfl_xor_sync(0xffffffffu, mx0, 2));
        mx1 = fmaxf(mx1, __shfl_xor_sync(0xffffffffu, mx1, 1));
        mx1 = fmaxf(mx1, __shfl_xor_sync(0xffffffffu, mx1, 2));
        const float mn0 = fmaxf(m_0, mx0);
        const float mn1 = fmaxf(m_1, mx1);
        const float al0 = __expf(m_0 - mn0);
        const float al1 = __expf(m_1 - mn1);
        float rs0 = 0.0f, rs1 = 0.0f;
        #pragma unroll
        for (int ni = 0; ni < 8; ni++) {
            sa[ni][0] = __expf(sa[ni][0] - mn0);
            sa[ni][1] = __expf(sa[ni][1] - mn0);
            sa[ni][2] = __expf(sa[ni][2] - mn1);
            sa[ni][3] = __expf(sa[ni][3] - mn1);
            rs0 += sa[ni][0] + sa[ni][1];
            rs1 += sa[ni][2] + sa[ni][3];
        }
        rs0 += __shfl_xor_sync(0xffffffffu, rs0, 1);
        rs0 += __shfl_xor_sync(0xffffffffu, rs0, 2);
        rs1 += __shfl_xor_sync(0xffffffffu, rs1, 1);
        rs1 += __shfl_xor_sync(0xffffffffu, rs1, 2);
        l_0 = l_0 * al0 + rs0;
        l_1 = l_1 * al1 + rs1;
        m_0 = mn0; m_1 = mn1;
        #pragma unroll
        for (int ni = 0; ni < 8; ni++) {
            oacc[ni][0] *= al0; oacc[ni][1] *= al0;
            oacc[ni][2] *= al1; oacc[ni][3] *= al1;
        }

        uint32_t* sP = sQ;
        #pragma unroll
        for (int ni = 0; ni < 8; ni++) {
            const int c = ni * 8 + 2 * q;
            sP[(mrow + g) * QP_ST + c]         = f2tf32(sa[ni][0]);
            sP[(mrow + g) * QP_ST + c + 1]     = f2tf32(sa[ni][1]);
            sP[(mrow + g + 8) * QP_ST + c]     = f2tf32(sa[ni][2]);
            sP[(mrow + g + 8) * QP_ST + c + 1] = f2tf32(sa[ni][3]);
        }
        __syncwarp();

        #pragma unroll
        for (int ks = 0; ks < 8; ks++) {
            uint32_t pa[4];
            pa[0] = sP[(mrow + g) * QP_ST + ks * 8 + q];
            pa[1] = sP[(mrow + g + 8) * QP_ST + ks * 8 + q];
            pa[2] = sP[(mrow + g) * QP_ST + ks * 8 + q + 4];
            pa[3] = sP[(mrow + g + 8) * QP_ST + ks * 8 + q + 4];
            #pragma unroll
            for (int ni = 0; ni < 8; ni++) {
                uint32_t b0 = sV[(ks * 8 + q) * KV_ST + ni * 8 + g];
                uint32_t b1 = sV[(ks * 8 + q + 4) * KV_ST + ni * 8 + g];
                mma_tf32(oacc[ni], pa, b0, b1);
            }
        }
        __syncthreads();
    }

    // normalize + write y (tf32-rounded so proj reads raw)
    const float il0 = 1.0f / l_0;
    const float il1 = 1.0f / l_1;
    const int t0 = q0 + mrow + g;
    const int t1 = t0 + 8;
    #pragma unroll
    for (int ni = 0; ni < 8; ni++) {
        const int col = h * HD + ni * 8 + 2 * q;
        uint2 v0 = make_uint2(f2tf32(oacc[ni][0] * il0), f2tf32(oacc[ni][1] * il0));
        uint2 v1 = make_uint2(f2tf32(oacc[ni][2] * il1), f2tf32(oacc[ni][3] * il1));
        *reinterpret_cast<uint2*>(&y[(size_t)(b * TT + t0) * CC + col]) = v0;
        *reinterpret_cast<uint2*>(&y[(size_t)(b * TT + t1) * CC + col]) = v1;
    }
}

// ---------------------------------------------------------------------------
extern "C" void kernel_launch(void* const* d_in, const int* in_sizes, int n_in,
                              void* d_out, int out_size) {
    (void)in_sizes; (void)n_in; (void)out_size;
    const float* x      = (const float*)d_in[0];
    const float* W_kqv  = (const float*)d_in[1];
    const float* b_kqv  = (const float*)d_in[2];
    const float* W_proj = (const float*)d_in[3];
    const float* b_proj = (const float*)d_in[4];
    float* out = (float*)d_out;

    float *kqv = nullptr, *y = nullptr, *xtf = nullptr, *wk = nullptr, *wp = nullptr;
    cudaGetSymbolAddress((void**)&kqv, g_kqv);
    cudaGetSymbolAddress((void**)&y, g_y);
    cudaGetSymbolAddress((void**)&xtf, g_xtf);
    cudaGetSymbolAddress((void**)&wk, g_wk);
    cudaGetSymbolAddress((void**)&wp, g_wp);

    cudaFuncSetAttribute(gemm_tf32<true>, cudaFuncAttributeMaxDynamicSharedMemorySize,
                         GSMEM_BYTES);
    cudaFuncSetAttribute(gemm_tf32<false>, cudaFuncAttributeMaxDynamicSharedMemorySize,
                         GSMEM_BYTES);
    cudaFuncSetAttribute(attn_tc_kernel, cudaFuncAttributeMaxDynamicSharedMemorySize,
                         ATT_BYTES);

    // 0) pre-round inputs to tf32
    {
        int n4x = (BT * CC) / 4;
        cvt_tf32_kernel<<<(n4x + 255) / 256, 256>>>(
            (const float4*)x, (uint4*)xtf, n4x);
        int n4k = (KQV3 * CC) / 4;
        cvt_tf32_kernel<<<(n4k + 255) / 256, 256>>>(
            (const float4*)W_kqv, (uint4*)wk, n4k);
        int n4p = (CC * CC) / 4;
        cvt_tf32_kernel<<<(n4p + 255) / 256, 256>>>(
            (const float4*)W_proj, (uint4*)wp, n4p);
    }
    // 1) kqv = x @ W_kqv^T + b_kqv  (epilogue tf32-rounds)
    {
        dim3 grid(KQV3 / 128, BT / 128);
        gemm_tf32<true><<<grid, 256, GSMEM_BYTES>>>(xtf, wk, b_kqv, kqv,
                                                    BT, KQV3, CC);
    }
    // 2) flash attention -> y (tf32-rounded)
    {
        dim3 grid(TT / 64, NH, BB);
        attn_tc_kernel<<<grid, 128, ATT_BYTES>>>(kqv, y);
    }
    // 3) out = y @ W_proj^T + b_proj (plain fp32 epilogue)
    {
        dim3 grid(CC / 128, BT / 128);
        gemm_tf32<false><<<grid, 256, GSMEM_BYTES>>>(y, wp, b_proj, out,
                                                     BT, CC, CC);
    }
}

// round 9
// speedup vs baseline: 1.0073x; 1.0073x over previous
#include <cuda_runtime.h>
#include <math.h>
#include <stdint.h>

// Problem constants
#define BB   2
#define TT   2048
#define CC   1024
#define NH   16
#define HD   64
#define BT   (BB * TT)        // 4096
#define KQV3 (3 * CC)         // 3072

// Scratch (allocation-free rule: __device__ globals)
__device__ float g_kqv[(size_t)BT * KQV3];   // qkv activations (tf32-rounded)
__device__ float g_y[(size_t)BT * CC];       // attention out (tf32-rounded)
__device__ float g_xtf[(size_t)BT * CC];     // x, tf32-rounded
__device__ float g_wk[(size_t)KQV3 * CC];    // W_kqv, tf32-rounded
__device__ float g_wp[(size_t)CC * CC];      // W_proj, tf32-rounded

// ---------------------------------------------------------------------------
// Helpers
// ---------------------------------------------------------------------------
__device__ __forceinline__ uint32_t f2tf32(float x) {
    uint32_t r;
    asm("cvt.rna.tf32.f32 %0, %1;" : "=r"(r) : "f"(x));
    return r;
}

__device__ __forceinline__ void mma_tf32(float* c, const uint32_t* a,
                                         uint32_t b0, uint32_t b1) {
    asm volatile(
        "mma.sync.aligned.m16n8k8.row.col.f32.tf32.tf32.f32 "
        "{%0,%1,%2,%3}, {%4,%5,%6,%7}, {%8,%9}, {%0,%1,%2,%3};\n"
        : "+f"(c[0]), "+f"(c[1]), "+f"(c[2]), "+f"(c[3])
        : "r"(a[0]), "r"(a[1]), "r"(a[2]), "r"(a[3]), "r"(b0), "r"(b1));
}

__device__ __forceinline__ void cpa16(uint32_t saddr, const void* gptr) {
    asm volatile("cp.async.cg.shared.global [%0], [%1], 16;" :: "r"(saddr), "l"(gptr));
}
__device__ __forceinline__ void cpcommit() {
    asm volatile("cp.async.commit_group;" ::: "memory");
}
template <int N>
__device__ __forceinline__ void cpwait() {
    asm volatile("cp.async.wait_group %0;" :: "n"(N) : "memory");
}

// ---------------------------------------------------------------------------
// Pre-pass: tf32-round an fp32 array (vectorized).
// ---------------------------------------------------------------------------
__global__ __launch_bounds__(256)
void cvt_tf32_kernel(const float4* __restrict__ src, uint4* __restrict__ dst,
                     int n4) {
    const int i = blockIdx.x * blockDim.x + threadIdx.x;
    if (i < n4) {
        float4 v = src[i];
        uint4 o;
        o.x = f2tf32(v.x); o.y = f2tf32(v.y);
        o.z = f2tf32(v.z); o.w = f2tf32(v.w);
        dst[i] = o;
    }
}

// ---------------------------------------------------------------------------
// tf32 tensor-core GEMM, 3-stage cp.async pipeline, BK=32.
// C[m,n] = sum_k A[m,k]*W[n,k] + bias[n]. Inputs PRE-ROUNDED tf32.
// BM=BN=128. 256 thr, 8 warps (2m x 4n), warp tile 64x32.
// smem [row][k] stride 36 -> fragment bank (4g+q) mod 32 all-distinct.
// ---------------------------------------------------------------------------
#define GPAD     36
#define GTILEW   (128 * GPAD)          // 4608 words / operand tile
#define GSTAGEW  (2 * GTILEW)          // 9216 words / stage (A+W)
#define GSTAGES  3
#define GSMEM_BYTES (GSTAGES * GSTAGEW * 4)   // 110592

template <bool EPI_CVT>
__global__ __launch_bounds__(256)
void gemm_tf32(const float* __restrict__ A, const float* __restrict__ W,
               const float* __restrict__ bias, float* __restrict__ Cmat,
               int M, int N, int K) {
    extern __shared__ uint32_t gsm[];

    const int tid  = threadIdx.x;
    const int lane = tid & 31;
    const int wid  = tid >> 5;
    const int g    = lane >> 2;
    const int q    = lane & 3;
    const int wm   = wid >> 2;
    const int wn   = wid & 3;

    const int m0 = blockIdx.y * 128;
    const int n0 = blockIdx.x * 128;
    const float* Abase = A + (size_t)m0 * K;
    const float* Wbase = W + (size_t)n0 * K;
    const int niter = K >> 5;   // K/32

    // chunk c (0..1023) -> row c>>3, float-offset (c&7)*4
    const int rr[4] = { tid >> 3, (tid + 256) >> 3, (tid + 512) >> 3, (tid + 768) >> 3 };
    const int kk[4] = { (tid & 7) << 2, ((tid + 256) & 7) << 2,
                        ((tid + 512) & 7) << 2, ((tid + 768) & 7) << 2 };

    float acc[4][4][4];
    #pragma unroll
    for (int mi = 0; mi < 4; mi++)
        #pragma unroll
        for (int ni = 0; ni < 4; ni++)
            #pragma unroll
            for (int r = 0; r < 4; r++) acc[mi][ni][r] = 0.0f;

    auto issueTile = [&](int t) {
        uint32_t sb = (uint32_t)__cvta_generic_to_shared(
            gsm + (t % GSTAGES) * GSTAGEW);
        #pragma unroll
        for (int j = 0; j < 4; j++) {
            const int row = rr[j], kc = kk[j];
            cpa16(sb + (row * GPAD + kc) * 4,
                  Abase + (size_t)row * K + t * 32 + kc);
            cpa16(sb + (GTILEW + row * GPAD + kc) * 4,
                  Wbase + (size_t)row * K + t * 32 + kc);
        }
    };

    // prologue: tiles 0,1
    #pragma unroll
    for (int p = 0; p < GSTAGES - 1; p++) {
        if (p < niter) issueTile(p);
        cpcommit();
    }

    for (int i = 0; i < niter; i++) {
        if (i + 2 < niter) issueTile(i + 2);
        cpcommit();
        cpwait<GSTAGES - 1>();   // tile i resident
        __syncthreads();

        const uint32_t* sa = gsm + (i % GSTAGES) * GSTAGEW;
        const uint32_t* sw = sa + GTILEW;

        #pragma unroll
        for (int ks = 0; ks < 32; ks += 8) {
            uint32_t af[4][4];
            uint32_t bf[4][2];
            #pragma unroll
            for (int mi = 0; mi < 4; mi++) {
                const int m = wm * 64 + mi * 16;
                af[mi][0] = sa[(m + g) * GPAD + ks + q];
                af[mi][1] = sa[(m + g + 8) * GPAD + ks + q];
                af[mi][2] = sa[(m + g) * GPAD + ks + q + 4];
                af[mi][3] = sa[(m + g + 8) * GPAD + ks + q + 4];
            }
            #pragma unroll
            for (int ni = 0; ni < 4; ni++) {
                const int n = wn * 32 + ni * 8;
                bf[ni][0] = sw[(n + g) * GPAD + ks + q];
                bf[ni][1] = sw[(n + g) * GPAD + ks + q + 4];
            }
            #pragma unroll
            for (int mi = 0; mi < 4; mi++)
                #pragma unroll
                for (int ni = 0; ni < 4; ni++)
                    mma_tf32(acc[mi][ni], af[mi], bf[ni][0], bf[ni][1]);
        }
        __syncthreads();   // stage i%3 fully read before tile i+3 overwrites
    }

    #pragma unroll
    for (int mi = 0; mi < 4; mi++) {
        const int m = m0 + wm * 64 + mi * 16 + g;
        #pragma unroll
        for (int ni = 0; ni < 4; ni++) {
            const int n = n0 + wn * 32 + ni * 8 + 2 * q;
            const float b0 = __ldg(&bias[n]);
            const float b1 = __ldg(&bias[n + 1]);
            float o00 = acc[mi][ni][0] + b0, o01 = acc[mi][ni][1] + b1;
            float o10 = acc[mi][ni][2] + b0, o11 = acc[mi][ni][3] + b1;
            if (EPI_CVT) {
                o00 = __uint_as_float(f2tf32(o00));
                o01 = __uint_as_float(f2tf32(o01));
                o10 = __uint_as_float(f2tf32(o10));
                o11 = __uint_as_float(f2tf32(o11));
            }
            *reinterpret_cast<float2*>(&Cmat[(size_t)m * N + n]) =
                make_float2(o00, o01);
            *reinterpret_cast<float2*>(&Cmat[(size_t)(m + 8) * N + n]) =
                make_float2(o10, o11);
        }
    }
}

// ---------------------------------------------------------------------------
// Flash attention, tf32 mma, q-tile 128 rows, 256 threads (8 warps).
// Each warp owns 16 q-rows; K/V tiles of 64 keys double-buffered via cp.async.
// sQ [128][68] raw fp32 (reused as tf32 sP); sK,sV [64][72], 2 stages.
// ---------------------------------------------------------------------------
#define QROWS 128
#define QP_ST 68
#define KV_ST 72
#define QW  (QROWS * QP_ST)     // 8704 words
#define KVW (64 * KV_ST)        // 4608 words
#define ASTW (2 * KVW)          // 9216 words / stage
#define ATT_BYTES ((QW + 2 * ASTW) * 4)   // 108544

__global__ __launch_bounds__(256)
void attn_tc_kernel(const float* __restrict__ kqv, float* __restrict__ y) {
    extern __shared__ uint32_t smem[];
    uint32_t* sQ = smem;

    const int qb  = blockIdx.x;
    const int h   = blockIdx.y;
    const int b   = blockIdx.z;
    const int tid = threadIdx.x;
    const int w   = tid >> 5;
    const int lane = tid & 31;
    const int g   = lane >> 2;
    const int q   = lane & 3;
    const int q0  = qb * QROWS;
    const int mrow = 16 * w;
    const float scale = 0.125f;

    const size_t tokStride = (size_t)NH * 3 * HD;
    const size_t headOff   = (size_t)h * 3 * HD;

    auto issueKV = [&](int kb) {
        const int k0 = kb * 64;
        uint32_t base = (uint32_t)__cvta_generic_to_shared(
            smem + QW + (kb & 1) * ASTW);
        #pragma unroll
        for (int j = 0; j < 4; j++) {
            const int c   = tid + j * 256;
            const int row = c >> 4;
            const int c4  = (c & 15) << 2;
            const float* gk =
                &kqv[((size_t)(b * TT + k0 + row)) * tokStride + headOff + c4];
            cpa16(base + (row * KV_ST + c4) * 4, gk);                 // K
            cpa16(base + (KVW + row * KV_ST + c4) * 4, gk + 2 * HD);  // V
        }
    };

    issueKV(0);
    cpcommit();

    // load Q tile (raw tf32-rounded fp32)
    for (int idx = tid; idx < QROWS * 16; idx += 256) {
        const int row = idx >> 4;
        const int c4  = (idx & 15) << 2;
        uint4 v = *reinterpret_cast<const uint4*>(
            &kqv[((size_t)(b * TT + q0 + row)) * tokStride + headOff + HD + c4]);
        uint32_t* dst = &sQ[row * QP_ST + c4];
        dst[0] = v.x; dst[1] = v.y; dst[2] = v.z; dst[3] = v.w;
    }
    __syncthreads();

    uint32_t qf[8][4];
    #pragma unroll
    for (int ks = 0; ks < 8; ks++) {
        qf[ks][0] = sQ[(mrow + g) * QP_ST + ks * 8 + q];
        qf[ks][1] = sQ[(mrow + g + 8) * QP_ST + ks * 8 + q];
        qf[ks][2] = sQ[(mrow + g) * QP_ST + ks * 8 + q + 4];
        qf[ks][3] = sQ[(mrow + g + 8) * QP_ST + ks * 8 + q + 4];
    }

    float oacc[8][4];
    #pragma unroll
    for (int ni = 0; ni < 8; ni++)
        #pragma unroll
        for (int r = 0; r < 4; r++) oacc[ni][r] = 0.0f;
    float m_0 = -1e30f, m_1 = -1e30f, l_0 = 0.0f, l_1 = 0.0f;

    const int qrow0 = q0 + mrow + g;
    const int qrow1 = qrow0 + 8;
    const int nkb = 2 * (qb + 1);   // 64-key tiles covering keys <= q0+127

    for (int kb = 0; kb < nkb; kb++) {
        const int k0 = kb * 64;
        if (kb + 1 < nkb) issueKV(kb + 1);
        cpcommit();
        cpwait<1>();
        __syncthreads();

        const uint32_t* sK = smem + QW + (kb & 1) * ASTW;
        const uint32_t* sV = sK + KVW;

        float sa[8][4];
        #pragma unroll
        for (int ni = 0; ni < 8; ni++)
            #pragma unroll
            for (int r = 0; r < 4; r++) sa[ni][r] = 0.0f;

        #pragma unroll
        for (int ks = 0; ks < 8; ks++) {
            #pragma unroll
            for (int ni = 0; ni < 8; ni++) {
                uint32_t b0 = sK[(ni * 8 + g) * KV_ST + ks * 8 + q];
                uint32_t b1 = sK[(ni * 8 + g) * KV_ST + ks * 8 + q + 4];
                mma_tf32(sa[ni], qf[ks], b0, b1);
            }
        }

        const bool diag = (kb >= 2 * qb);   // only last two tiles can cross
        #pragma unroll
        for (int ni = 0; ni < 8; ni++) {
            const int key = k0 + ni * 8 + 2 * q;
            sa[ni][0] = (diag && key     > qrow0) ? -1e30f : sa[ni][0] * scale;
            sa[ni][1] = (diag && key + 1 > qrow0) ? -1e30f : sa[ni][1] * scale;
            sa[ni][2] = (diag && key     > qrow1) ? -1e30f : sa[ni][2] * scale;
            sa[ni][3] = (diag && key + 1 > qrow1) ? -1e30f : sa[ni][3] * scale;
        }

        float mx0 = -1e30f, mx1 = -1e30f;
        #pragma unroll
        for (int ni = 0; ni < 8; ni++) {
            mx0 = fmaxf(mx0, fmaxf(sa[ni][0], sa[ni][1]));
            mx1 = fmaxf(mx1, fmaxf(sa[ni][2], sa[ni][3]));
        }
        mx0 = fmaxf(mx0, __shfl_xor_sync(0xffffffffu, mx0, 1));
        mx0 = fmaxf(mx0, __shfl_xor_sync(0xffffffffu, mx0, 2));
        mx1 = fmaxf(mx1, __shfl_xor_sync(0xffffffffu, mx1, 1));
        mx1 = fmaxf(mx1, __shfl_xor_sync(0xffffffffu, mx1, 2));
        const float mn0 = fmaxf(m_0, mx0);
        const float mn1 = fmaxf(m_1, mx1);
        const float al0 = __expf(m_0 - mn0);
        const float al1 = __expf(m_1 - mn1);
        float rs0 = 0.0f, rs1 = 0.0f;
        #pragma unroll
        for (int ni = 0; ni < 8; ni++) {
            sa[ni][0] = __expf(sa[ni][0] - mn0);
            sa[ni][1] = __expf(sa[ni][1] - mn0);
            sa[ni][2] = __expf(sa[ni][2] - mn1);
            sa[ni][3] = __expf(sa[ni][3] - mn1);
            rs0 += sa[ni][0] + sa[ni][1];
            rs1 += sa[ni][2] + sa[ni][3];
        }
        rs0 += __shfl_xor_sync(0xffffffffu, rs0, 1);
        rs0 += __shfl_xor_sync(0xffffffffu, rs0, 2);
        rs1 += __shfl_xor_sync(0xffffffffu, rs1, 1);
        rs1 += __shfl_xor_sync(0xffffffffu, rs1, 2);
        l_0 = l_0 * al0 + rs0;
        l_1 = l_1 * al1 + rs1;
        m_0 = mn0; m_1 = mn1;
        #pragma unroll
        for (int ni = 0; ni < 8; ni++) {
            oacc[ni][0] *= al0; oacc[ni][1] *= al0;
            oacc[ni][2] *= al1; oacc[ni][3] *= al1;
        }

        uint32_t* sP = sQ;   // warp-private rows
        #pragma unroll
        for (int ni = 0; ni < 8; ni++) {
            const int c = ni * 8 + 2 * q;
            sP[(mrow + g) * QP_ST + c]         = f2tf32(sa[ni][0]);
            sP[(mrow + g) * QP_ST + c + 1]     = f2tf32(sa[ni][1]);
            sP[(mrow + g + 8) * QP_ST + c]     = f2tf32(sa[ni][2]);
            sP[(mrow + g + 8) * QP_ST + c + 1] = f2tf32(sa[ni][3]);
        }
        __syncwarp();

        #pragma unroll
        for (int ks = 0; ks < 8; ks++) {
            uint32_t pa[4];
            pa[0] = sP[(mrow + g) * QP_ST + ks * 8 + q];
            pa[1] = sP[(mrow + g + 8) * QP_ST + ks * 8 + q];
            pa[2] = sP[(mrow + g) * QP_ST + ks * 8 + q + 4];
            pa[3] = sP[(mrow + g + 8) * QP_ST + ks * 8 + q + 4];
            #pragma unroll
            for (int ni = 0; ni < 8; ni++) {
                uint32_t b0 = sV[(ks * 8 + q) * KV_ST + ni * 8 + g];
                uint32_t b1 = sV[(ks * 8 + q + 4) * KV_ST + ni * 8 + g];
                mma_tf32(oacc[ni], pa, b0, b1);
            }
        }
        __syncthreads();
    }

    const float il0 = 1.0f / l_0;
    const float il1 = 1.0f / l_1;
    const int t0 = q0 + mrow + g;
    const int t1 = t0 + 8;
    #pragma unroll
    for (int ni = 0; ni < 8; ni++) {
        const int col = h * HD + ni * 8 + 2 * q;
        uint2 v0 = make_uint2(f2tf32(oacc[ni][0] * il0), f2tf32(oacc[ni][1] * il0));
        uint2 v1 = make_uint2(f2tf32(oacc[ni][2] * il1), f2tf32(oacc[ni][3] * il1));
        *reinterpret_cast<uint2*>(&y[(size_t)(b * TT + t0) * CC + col]) = v0;
        *reinterpret_cast<uint2*>(&y[(size_t)(b * TT + t1) * CC + col]) = v1;
    }
}

// ---------------------------------------------------------------------------
extern "C" void kernel_launch(void* const* d_in, const int* in_sizes, int n_in,
                              void* d_out, int out_size) {
    (void)in_sizes; (void)n_in; (void)out_size;
    const float* x      = (const float*)d_in[0];
    const float* W_kqv  = (const float*)d_in[1];
    const float* b_kqv  = (const float*)d_in[2];
    const float* W_proj = (const float*)d_in[3];
    const float* b_proj = (const float*)d_in[4];
    float* out = (float*)d_out;

    float *kqv = nullptr, *y = nullptr, *xtf = nullptr, *wk = nullptr, *wp = nullptr;
    cudaGetSymbolAddress((void**)&kqv, g_kqv);
    cudaGetSymbolAddress((void**)&y, g_y);
    cudaGetSymbolAddress((void**)&xtf, g_xtf);
    cudaGetSymbolAddress((void**)&wk, g_wk);
    cudaGetSymbolAddress((void**)&wp, g_wp);

    cudaFuncSetAttribute(gemm_tf32<true>, cudaFuncAttributeMaxDynamicSharedMemorySize,
                         GSMEM_BYTES);
    cudaFuncSetAttribute(gemm_tf32<false>, cudaFuncAttributeMaxDynamicSharedMemorySize,
                         GSMEM_BYTES);
    cudaFuncSetAttribute(attn_tc_kernel, cudaFuncAttributeMaxDynamicSharedMemorySize,
                         ATT_BYTES);

    // 0) pre-round inputs to tf32
    {
        int n4x = (BT * CC) / 4;
        cvt_tf32_kernel<<<(n4x + 255) / 256, 256>>>(
            (const float4*)x, (uint4*)xtf, n4x);
        int n4k = (KQV3 * CC) / 4;
        cvt_tf32_kernel<<<(n4k + 255) / 256, 256>>>(
            (const float4*)W_kqv, (uint4*)wk, n4k);
        int n4p = (CC * CC) / 4;
        cvt_tf32_kernel<<<(n4p + 255) / 256, 256>>>(
            (const float4*)W_proj, (uint4*)wp, n4p);
    }
    // 1) kqv = x @ W_kqv^T + b_kqv  (epilogue tf32-rounds)
    {
        dim3 grid(KQV3 / 128, BT / 128);
        gemm_tf32<true><<<grid, 256, GSMEM_BYTES>>>(xtf, wk, b_kqv, kqv,
                                                    BT, KQV3, CC);
    }
    // 2) flash attention -> y (tf32-rounded)
    {
        dim3 grid(TT / QROWS, NH, BB);
        attn_tc_kernel<<<grid, 256, ATT_BYTES>>>(kqv, y);
    }
    // 3) out = y @ W_proj^T + b_proj (plain fp32 epilogue)
    {
        dim3 grid(CC / 128, BT / 128);
        gemm_tf32<false><<<grid, 256, GSMEM_BYTES>>>(y, wp, b_proj, out,
                                                     BT, CC, CC);
    }
}

// round 10
// speedup vs baseline: 1.1573x; 1.1489x over previous
#include <cuda_runtime.h>
#include <math.h>
#include <stdint.h>

// Problem constants
#define BB   2
#define TT   2048
#define CC   1024
#define NH   16
#define HD   64
#define BT   (BB * TT)        // 4096
#define KQV3 (3 * CC)         // 3072

// Scratch (allocation-free rule: __device__ globals)
__device__ float g_kqv[(size_t)BT * KQV3];   // qkv activations (tf32-rounded)
__device__ float g_y[(size_t)BT * CC];       // attention out (tf32-rounded)
__device__ float g_xtf[(size_t)BT * CC];     // x, tf32-rounded
__device__ float g_wk[(size_t)KQV3 * CC];    // W_kqv, tf32-rounded
__device__ float g_wp[(size_t)CC * CC];      // W_proj, tf32-rounded

// ---------------------------------------------------------------------------
// Helpers
// ---------------------------------------------------------------------------
__device__ __forceinline__ uint32_t f2tf32(float x) {
    uint32_t r;
    asm("cvt.rna.tf32.f32 %0, %1;" : "=r"(r) : "f"(x));
    return r;
}

__device__ __forceinline__ void mma_tf32(float* c, const uint32_t* a,
                                         uint32_t b0, uint32_t b1) {
    asm volatile(
        "mma.sync.aligned.m16n8k8.row.col.f32.tf32.tf32.f32 "
        "{%0,%1,%2,%3}, {%4,%5,%6,%7}, {%8,%9}, {%0,%1,%2,%3};\n"
        : "+f"(c[0]), "+f"(c[1]), "+f"(c[2]), "+f"(c[3])
        : "r"(a[0]), "r"(a[1]), "r"(a[2]), "r"(a[3]), "r"(b0), "r"(b1));
}

__device__ __forceinline__ void cpa16(uint32_t saddr, const void* gptr) {
    asm volatile("cp.async.cg.shared.global [%0], [%1], 16;" :: "r"(saddr), "l"(gptr));
}
__device__ __forceinline__ void cpcommit() {
    asm volatile("cp.async.commit_group;" ::: "memory");
}
template <int N>
__device__ __forceinline__ void cpwait() {
    asm volatile("cp.async.wait_group %0;" :: "n"(N) : "memory");
}

// ---------------------------------------------------------------------------
// Pre-pass: tf32-round an fp32 array (vectorized).
// ---------------------------------------------------------------------------
__global__ __launch_bounds__(256)
void cvt_tf32_kernel(const float4* __restrict__ src, uint4* __restrict__ dst,
                     int n4) {
    const int i = blockIdx.x * blockDim.x + threadIdx.x;
    if (i < n4) {
        float4 v = src[i];
        uint4 o;
        o.x = f2tf32(v.x); o.y = f2tf32(v.y);
        o.z = f2tf32(v.z); o.w = f2tf32(v.w);
        dst[i] = o;
    }
}

// ---------------------------------------------------------------------------
// tf32 tensor-core GEMM, 3-stage cp.async pipeline, BK=32.
// C[m,n] = sum_k A[m,k]*W[n,k] + bias[n]. Inputs PRE-ROUNDED tf32.
// BM=BN=128. 128 thr, 4 warps (2m x 2n), warp tile 64x64.
// smem [row][k] stride 36 -> fragment bank (4g+q) mod 32 all-distinct.
// ---------------------------------------------------------------------------
#define GPAD     36
#define GTILEW   (128 * GPAD)          // 4608 words / operand tile
#define GSTAGEW  (2 * GTILEW)          // 9216 words / stage (A+W)
#define GSTAGES  3
#define GSMEM_BYTES (GSTAGES * GSTAGEW * 4)   // 110592

template <bool EPI_CVT>
__global__ __launch_bounds__(128)
void gemm_tf32(const float* __restrict__ A, const float* __restrict__ W,
               const float* __restrict__ bias, float* __restrict__ Cmat,
               int M, int N, int K) {
    extern __shared__ uint32_t gsm[];

    const int tid  = threadIdx.x;
    const int lane = tid & 31;
    const int wid  = tid >> 5;
    const int g    = lane >> 2;
    const int q    = lane & 3;
    const int wm   = wid >> 1;    // 0..1
    const int wn   = wid & 1;     // 0..1

    const int m0 = blockIdx.y * 128;
    const int n0 = blockIdx.x * 128;
    const float* Abase = A + (size_t)m0 * K;
    const float* Wbase = W + (size_t)n0 * K;
    const int niter = K >> 5;   // K/32

    float acc[4][8][4];
    #pragma unroll
    for (int mi = 0; mi < 4; mi++)
        #pragma unroll
        for (int ni = 0; ni < 8; ni++)
            #pragma unroll
            for (int r = 0; r < 4; r++) acc[mi][ni][r] = 0.0f;

    auto issueTile = [&](int t) {
        uint32_t sb = (uint32_t)__cvta_generic_to_shared(
            gsm + (t % GSTAGES) * GSTAGEW);
        #pragma unroll
        for (int j = 0; j < 8; j++) {
            const int c   = tid + j * 128;     // 0..1023
            const int row = c >> 3;
            const int kc  = (c & 7) << 2;
            cpa16(sb + (row * GPAD + kc) * 4,
                  Abase + (size_t)row * K + t * 32 + kc);
            cpa16(sb + (GTILEW + row * GPAD + kc) * 4,
                  Wbase + (size_t)row * K + t * 32 + kc);
        }
    };

    // prologue: tiles 0,1
    #pragma unroll
    for (int p = 0; p < GSTAGES - 1; p++) {
        if (p < niter) issueTile(p);
        cpcommit();
    }

    for (int i = 0; i < niter; i++) {
        if (i + 2 < niter) issueTile(i + 2);
        cpcommit();
        cpwait<GSTAGES - 1>();   // tile i resident
        __syncthreads();

        const uint32_t* sa = gsm + (i % GSTAGES) * GSTAGEW;
        const uint32_t* sw = sa + GTILEW;

        #pragma unroll
        for (int ks = 0; ks < 32; ks += 8) {
            uint32_t af[4][4];
            uint32_t bf[8][2];
            #pragma unroll
            for (int mi = 0; mi < 4; mi++) {
                const int m = wm * 64 + mi * 16;
                af[mi][0] = sa[(m + g) * GPAD + ks + q];
                af[mi][1] = sa[(m + g + 8) * GPAD + ks + q];
                af[mi][2] = sa[(m + g) * GPAD + ks + q + 4];
                af[mi][3] = sa[(m + g + 8) * GPAD + ks + q + 4];
            }
            #pragma unroll
            for (int ni = 0; ni < 8; ni++) {
                const int n = wn * 64 + ni * 8;
                bf[ni][0] = sw[(n + g) * GPAD + ks + q];
                bf[ni][1] = sw[(n + g) * GPAD + ks + q + 4];
            }
            #pragma unroll
            for (int mi = 0; mi < 4; mi++)
                #pragma unroll
                for (int ni = 0; ni < 8; ni++)
                    mma_tf32(acc[mi][ni], af[mi], bf[ni][0], bf[ni][1]);
        }
        __syncthreads();   // stage i%3 fully read before tile i+3 overwrites
    }

    #pragma unroll
    for (int mi = 0; mi < 4; mi++) {
        const int m = m0 + wm * 64 + mi * 16 + g;
        #pragma unroll
        for (int ni = 0; ni < 8; ni++) {
            const int n = n0 + wn * 64 + ni * 8 + 2 * q;
            const float b0 = __ldg(&bias[n]);
            const float b1 = __ldg(&bias[n + 1]);
            float o00 = acc[mi][ni][0] + b0, o01 = acc[mi][ni][1] + b1;
            float o10 = acc[mi][ni][2] + b0, o11 = acc[mi][ni][3] + b1;
            if (EPI_CVT) {
                o00 = __uint_as_float(f2tf32(o00));
                o01 = __uint_as_float(f2tf32(o01));
                o10 = __uint_as_float(f2tf32(o10));
                o11 = __uint_as_float(f2tf32(o11));
            }
            *reinterpret_cast<float2*>(&Cmat[(size_t)m * N + n]) =
                make_float2(o00, o01);
            *reinterpret_cast<float2*>(&Cmat[(size_t)(m + 8) * N + n]) =
                make_float2(o10, o11);
        }
    }
}

// ---------------------------------------------------------------------------
// Flash attention, tf32 mma. 128 threads, 4 warps x 32 q-rows (mi=0,1).
// K/V fragment loads shared across both m-tiles -> per-row LDS halved.
// sQ [128][68] raw fp32 (reused as tf32 sP); sK,sV [64][72], 2 stages.
// ---------------------------------------------------------------------------
#define QROWS 128
#define QP_ST 68
#define KV_ST 72
#define QW  (QROWS * QP_ST)     // 8704 words
#define KVW (64 * KV_ST)        // 4608 words
#define ASTW (2 * KVW)          // 9216 words / stage
#define ATT_BYTES ((QW + 2 * ASTW) * 4)   // 108544

__global__ __launch_bounds__(128)
void attn_tc_kernel(const float* __restrict__ kqv, float* __restrict__ y) {
    extern __shared__ uint32_t smem[];
    uint32_t* sQ = smem;

    const int qb  = blockIdx.x;
    const int h   = blockIdx.y;
    const int b   = blockIdx.z;
    const int tid = threadIdx.x;
    const int w   = tid >> 5;
    const int lane = tid & 31;
    const int g   = lane >> 2;
    const int q   = lane & 3;
    const int q0  = qb * QROWS;
    const int mrow = 32 * w;          // 32 q-rows per warp
    const float scale = 0.125f;

    const size_t tokStride = (size_t)NH * 3 * HD;
    const size_t headOff   = (size_t)h * 3 * HD;

    auto issueKV = [&](int kb) {
        const int k0 = kb * 64;
        uint32_t base = (uint32_t)__cvta_generic_to_shared(
            smem + QW + (kb & 1) * ASTW);
        #pragma unroll
        for (int j = 0; j < 8; j++) {
            const int c   = tid + j * 128;
            const int row = c >> 4;
            const int c4  = (c & 15) << 2;
            const float* gk =
                &kqv[((size_t)(b * TT + k0 + row)) * tokStride + headOff + c4];
            cpa16(base + (row * KV_ST + c4) * 4, gk);                 // K
            cpa16(base + (KVW + row * KV_ST + c4) * 4, gk + 2 * HD);  // V
        }
    };

    issueKV(0);
    cpcommit();

    // load Q tile (raw tf32-rounded fp32)
    for (int idx = tid; idx < QROWS * 16; idx += 128) {
        const int row = idx >> 4;
        const int c4  = (idx & 15) << 2;
        uint4 v = *reinterpret_cast<const uint4*>(
            &kqv[((size_t)(b * TT + q0 + row)) * tokStride + headOff + HD + c4]);
        uint32_t* dst = &sQ[row * QP_ST + c4];
        dst[0] = v.x; dst[1] = v.y; dst[2] = v.z; dst[3] = v.w;
    }
    __syncthreads();

    // hoist Q fragments for both m-tiles
    uint32_t qf[2][8][4];
    #pragma unroll
    for (int mi = 0; mi < 2; mi++) {
        const int mr = mrow + mi * 16;
        #pragma unroll
        for (int ks = 0; ks < 8; ks++) {
            qf[mi][ks][0] = sQ[(mr + g) * QP_ST + ks * 8 + q];
            qf[mi][ks][1] = sQ[(mr + g + 8) * QP_ST + ks * 8 + q];
            qf[mi][ks][2] = sQ[(mr + g) * QP_ST + ks * 8 + q + 4];
            qf[mi][ks][3] = sQ[(mr + g + 8) * QP_ST + ks * 8 + q + 4];
        }
    }

    float oacc[2][8][4];
    #pragma unroll
    for (int mi = 0; mi < 2; mi++)
        #pragma unroll
        for (int ni = 0; ni < 8; ni++)
            #pragma unroll
            for (int r = 0; r < 4; r++) oacc[mi][ni][r] = 0.0f;
    float m_i[2][2], l_i[2][2];
    #pragma unroll
    for (int mi = 0; mi < 2; mi++) {
        m_i[mi][0] = -1e30f; m_i[mi][1] = -1e30f;
        l_i[mi][0] = 0.0f;   l_i[mi][1] = 0.0f;
    }

    const int nkb = 2 * (qb + 1);   // 64-key tiles covering keys <= q0+127

    for (int kb = 0; kb < nkb; kb++) {
        const int k0 = kb * 64;
        if (kb + 1 < nkb) issueKV(kb + 1);
        cpcommit();
        cpwait<1>();
        __syncthreads();

        const uint32_t* sK = smem + QW + (kb & 1) * ASTW;
        const uint32_t* sV = sK + KVW;

        // ---- S = Q K^T (K frags shared across both m-tiles) ----
        float sa[2][8][4];
        #pragma unroll
        for (int mi = 0; mi < 2; mi++)
            #pragma unroll
            for (int ni = 0; ni < 8; ni++)
                #pragma unroll
                for (int r = 0; r < 4; r++) sa[mi][ni][r] = 0.0f;

        #pragma unroll
        for (int ks = 0; ks < 8; ks++) {
            #pragma unroll
            for (int ni = 0; ni < 8; ni++) {
                uint32_t b0 = sK[(ni * 8 + g) * KV_ST + ks * 8 + q];
                uint32_t b1 = sK[(ni * 8 + g) * KV_ST + ks * 8 + q + 4];
                mma_tf32(sa[0][ni], qf[0][ks], b0, b1);
                mma_tf32(sa[1][ni], qf[1][ks], b0, b1);
            }
        }

        // ---- scale + causal mask + online softmax per m-tile ----
        const bool diag = (kb >= 2 * qb);
        #pragma unroll
        for (int mi = 0; mi < 2; mi++) {
            const int qr0 = q0 + mrow + mi * 16 + g;
            const int qr1 = qr0 + 8;
            #pragma unroll
            for (int ni = 0; ni < 8; ni++) {
                const int key = k0 + ni * 8 + 2 * q;
                sa[mi][ni][0] = (diag && key     > qr0) ? -1e30f : sa[mi][ni][0] * scale;
                sa[mi][ni][1] = (diag && key + 1 > qr0) ? -1e30f : sa[mi][ni][1] * scale;
                sa[mi][ni][2] = (diag && key     > qr1) ? -1e30f : sa[mi][ni][2] * scale;
                sa[mi][ni][3] = (diag && key + 1 > qr1) ? -1e30f : sa[mi][ni][3] * scale;
            }

            float mx0 = -1e30f, mx1 = -1e30f;
            #pragma unroll
            for (int ni = 0; ni < 8; ni++) {
                mx0 = fmaxf(mx0, fmaxf(sa[mi][ni][0], sa[mi][ni][1]));
                mx1 = fmaxf(mx1, fmaxf(sa[mi][ni][2], sa[mi][ni][3]));
            }
            mx0 = fmaxf(mx0, __shfl_xor_sync(0xffffffffu, mx0, 1));
            mx0 = fmaxf(mx0, __shfl_xor_sync(0xffffffffu, mx0, 2));
            mx1 = fmaxf(mx1, __shfl_xor_sync(0xffffffffu, mx1, 1));
            mx1 = fmaxf(mx1, __shfl_xor_sync(0xffffffffu, mx1, 2));
            const float mn0 = fmaxf(m_i[mi][0], mx0);
            const float mn1 = fmaxf(m_i[mi][1], mx1);
            const float al0 = __expf(m_i[mi][0] - mn0);
            const float al1 = __expf(m_i[mi][1] - mn1);
            float rs0 = 0.0f, rs1 = 0.0f;
            #pragma unroll
            for (int ni = 0; ni < 8; ni++) {
                sa[mi][ni][0] = __expf(sa[mi][ni][0] - mn0);
                sa[mi][ni][1] = __expf(sa[mi][ni][1] - mn0);
                sa[mi][ni][2] = __expf(sa[mi][ni][2] - mn1);
                sa[mi][ni][3] = __expf(sa[mi][ni][3] - mn1);
                rs0 += sa[mi][ni][0] + sa[mi][ni][1];
                rs1 += sa[mi][ni][2] + sa[mi][ni][3];
            }
            rs0 += __shfl_xor_sync(0xffffffffu, rs0, 1);
            rs0 += __shfl_xor_sync(0xffffffffu, rs0, 2);
            rs1 += __shfl_xor_sync(0xffffffffu, rs1, 1);
            rs1 += __shfl_xor_sync(0xffffffffu, rs1, 2);
            l_i[mi][0] = l_i[mi][0] * al0 + rs0;
            l_i[mi][1] = l_i[mi][1] * al1 + rs1;
            m_i[mi][0] = mn0; m_i[mi][1] = mn1;
            #pragma unroll
            for (int ni = 0; ni < 8; ni++) {
                oacc[mi][ni][0] *= al0; oacc[mi][ni][1] *= al0;
                oacc[mi][ni][2] *= al1; oacc[mi][ni][3] *= al1;
            }
        }

        // ---- write P (tf32) into sP (= sQ), warp-private rows ----
        uint32_t* sP = sQ;
        #pragma unroll
        for (int mi = 0; mi < 2; mi++) {
            const int mr = mrow + mi * 16;
            #pragma unroll
            for (int ni = 0; ni < 8; ni++) {
                const int c = ni * 8 + 2 * q;
                sP[(mr + g) * QP_ST + c]         = f2tf32(sa[mi][ni][0]);
                sP[(mr + g) * QP_ST + c + 1]     = f2tf32(sa[mi][ni][1]);
                sP[(mr + g + 8) * QP_ST + c]     = f2tf32(sa[mi][ni][2]);
                sP[(mr + g + 8) * QP_ST + c + 1] = f2tf32(sa[mi][ni][3]);
            }
        }
        __syncwarp();

        // ---- O += P @ V (V frags shared across both m-tiles) ----
        #pragma unroll
        for (int ks = 0; ks < 8; ks++) {
            uint32_t pa[2][4];
            #pragma unroll
            for (int mi = 0; mi < 2; mi++) {
                const int mr = mrow + mi * 16;
                pa[mi][0] = sP[(mr + g) * QP_ST + ks * 8 + q];
                pa[mi][1] = sP[(mr + g + 8) * QP_ST + ks * 8 + q];
                pa[mi][2] = sP[(mr + g) * QP_ST + ks * 8 + q + 4];
                pa[mi][3] = sP[(mr + g + 8) * QP_ST + ks * 8 + q + 4];
            }
            #pragma unroll
            for (int ni = 0; ni < 8; ni++) {
                uint32_t b0 = sV[(ks * 8 + q) * KV_ST + ni * 8 + g];
                uint32_t b1 = sV[(ks * 8 + q + 4) * KV_ST + ni * 8 + g];
                mma_tf32(oacc[0][ni], pa[0], b0, b1);
                mma_tf32(oacc[1][ni], pa[1], b0, b1);
            }
        }
        __syncthreads();
    }

    // ---- normalize + write y ----
    #pragma unroll
    for (int mi = 0; mi < 2; mi++) {
        const float il0 = 1.0f / l_i[mi][0];
        const float il1 = 1.0f / l_i[mi][1];
        const int t0 = q0 + mrow + mi * 16 + g;
        const int t1 = t0 + 8;
        #pragma unroll
        for (int ni = 0; ni < 8; ni++) {
            const int col = h * HD + ni * 8 + 2 * q;
            uint2 v0 = make_uint2(f2tf32(oacc[mi][ni][0] * il0),
                                  f2tf32(oacc[mi][ni][1] * il0));
            uint2 v1 = make_uint2(f2tf32(oacc[mi][ni][2] * il1),
                                  f2tf32(oacc[mi][ni][3] * il1));
            *reinterpret_cast<uint2*>(&y[(size_t)(b * TT + t0) * CC + col]) = v0;
            *reinterpret_cast<uint2*>(&y[(size_t)(b * TT + t1) * CC + col]) = v1;
        }
    }
}

// ---------------------------------------------------------------------------
extern "C" void kernel_launch(void* const* d_in, const int* in_sizes, int n_in,
                              void* d_out, int out_size) {
    (void)in_sizes; (void)n_in; (void)out_size;
    const float* x      = (const float*)d_in[0];
    const float* W_kqv  = (const float*)d_in[1];
    const float* b_kqv  = (const float*)d_in[2];
    const float* W_proj = (const float*)d_in[3];
    const float* b_proj = (const float*)d_in[4];
    float* out = (float*)d_out;

    float *kqv = nullptr, *y = nullptr, *xtf = nullptr, *wk = nullptr, *wp = nullptr;
    cudaGetSymbolAddress((void**)&kqv, g_kqv);
    cudaGetSymbolAddress((void**)&y, g_y);
    cudaGetSymbolAddress((void**)&xtf, g_xtf);
    cudaGetSymbolAddress((void**)&wk, g_wk);
    cudaGetSymbolAddress((void**)&wp, g_wp);

    cudaFuncSetAttribute(gemm_tf32<true>, cudaFuncAttributeMaxDynamicSharedMemorySize,
                         GSMEM_BYTES);
    cudaFuncSetAttribute(gemm_tf32<false>, cudaFuncAttributeMaxDynamicSharedMemorySize,
                         GSMEM_BYTES);
    cudaFuncSetAttribute(attn_tc_kernel, cudaFuncAttributeMaxDynamicSharedMemorySize,
                         ATT_BYTES);

    // 0) pre-round inputs to tf32
    {
        int n4x = (BT * CC) / 4;
        cvt_tf32_kernel<<<(n4x + 255) / 256, 256>>>(
            (const float4*)x, (uint4*)xtf, n4x);
        int n4k = (KQV3 * CC) / 4;
        cvt_tf32_kernel<<<(n4k + 255) / 256, 256>>>(
            (const float4*)W_kqv, (uint4*)wk, n4k);
        int n4p = (CC * CC) / 4;
        cvt_tf32_kernel<<<(n4p + 255) / 256, 256>>>(
            (const float4*)W_proj, (uint4*)wp, n4p);
    }
    // 1) kqv = x @ W_kqv^T + b_kqv  (epilogue tf32-rounds)
    {
        dim3 grid(KQV3 / 128, BT / 128);
        gemm_tf32<true><<<grid, 128, GSMEM_BYTES>>>(xtf, wk, b_kqv, kqv,
                                                    BT, KQV3, CC);
    }
    // 2) flash attention -> y (tf32-rounded)
    {
        dim3 grid(TT / QROWS, NH, BB);
        attn_tc_kernel<<<grid, 128, ATT_BYTES>>>(kqv, y);
    }
    // 3) out = y @ W_proj^T + b_proj (plain fp32 epilogue)
    {
        dim3 grid(CC / 128, BT / 128);
        gemm_tf32<false><<<grid, 128, GSMEM_BYTES>>>(y, wp, b_proj, out,
                                                     BT, CC, CC);
    }
}

// round 15
// speedup vs baseline: 1.2154x; 1.0502x over previous
#include <cuda_runtime.h>
#include <math.h>
#include <stdint.h>

// Problem constants
#define BB   2
#define TT   2048
#define CC   1024
#define NH   16
#define HD   64
#define BT   (BB * TT)        // 4096
#define KQV3 (3 * CC)         // 3072

// Scratch (allocation-free rule: __device__ globals)
__device__ float g_kqv[(size_t)BT * KQV3];   // qkv activations (tf32-rounded)
__device__ float g_y[(size_t)BT * CC];       // attention out (tf32-rounded)
__device__ float g_xtf[(size_t)BT * CC];     // x, tf32-rounded
__device__ float g_wk[(size_t)KQV3 * CC];    // W_kqv, tf32-rounded
__device__ float g_wp[(size_t)CC * CC];      // W_proj, tf32-rounded

// ---------------------------------------------------------------------------
// Helpers
// ---------------------------------------------------------------------------
__device__ __forceinline__ uint32_t f2tf32(float x) {
    uint32_t r;
    asm("cvt.rna.tf32.f32 %0, %1;" : "=r"(r) : "f"(x));
    return r;
}

__device__ __forceinline__ void mma_tf32(float* c, const uint32_t* a,
                                         uint32_t b0, uint32_t b1) {
    asm volatile(
        "mma.sync.aligned.m16n8k8.row.col.f32.tf32.tf32.f32 "
        "{%0,%1,%2,%3}, {%4,%5,%6,%7}, {%8,%9}, {%0,%1,%2,%3};\n"
        : "+f"(c[0]), "+f"(c[1]), "+f"(c[2]), "+f"(c[3])
        : "r"(a[0]), "r"(a[1]), "r"(a[2]), "r"(a[3]), "r"(b0), "r"(b1));
}

__device__ __forceinline__ void cpa16(uint32_t saddr, const void* gptr) {
    asm volatile("cp.async.cg.shared.global [%0], [%1], 16;" :: "r"(saddr), "l"(gptr));
}
__device__ __forceinline__ void cpcommit() {
    asm volatile("cp.async.commit_group;" ::: "memory");
}
template <int N>
__device__ __forceinline__ void cpwait() {
    asm volatile("cp.async.wait_group %0;" :: "n"(N) : "memory");
}

// ---------------------------------------------------------------------------
// Pre-pass: tf32-round an fp32 array (vectorized).
// ---------------------------------------------------------------------------
__global__ __launch_bounds__(256)
void cvt_tf32_kernel(const float4* __restrict__ src, uint4* __restrict__ dst,
                     int n4) {
    const int i = blockIdx.x * blockDim.x + threadIdx.x;
    if (i < n4) {
        float4 v = src[i];
        uint4 o;
        o.x = f2tf32(v.x); o.y = f2tf32(v.y);
        o.z = f2tf32(v.z); o.w = f2tf32(v.w);
        dst[i] = o;
    }
}

// ---------------------------------------------------------------------------
// tf32 tensor-core GEMM, 3-stage cp.async pipeline, BK=32.
// C[m,n] = sum_k A[m,k]*W[n,k] + bias[n]. Inputs PRE-ROUNDED tf32.
// BM=BN=128. 128 thr, 4 warps (2m x 2n), warp tile 64x64.
// ONE barrier per K-tile, issue-after-compute. With one commit per
// iteration the newest pending group at iter i's wait is tile i+1, so the
// wait must be cpwait<1> (all but newest) for tile i residency. Writes to
// stage (i+2)%3 = (i-1)%3 happen after sync(i); readers finished before it.
// Register double-buffered fragments hide LDS latency under MMAs.
// ---------------------------------------------------------------------------
#define GPAD     36
#define GTILEW   (128 * GPAD)          // 4608 words / operand tile
#define GSTAGEW  (2 * GTILEW)          // 9216 words / stage (A+W)
#define GSTAGES  3
#define GSMEM_BYTES (GSTAGES * GSTAGEW * 4)   // 110592

template <bool EPI_CVT>
__global__ __launch_bounds__(128)
void gemm_tf32(const float* __restrict__ A, const float* __restrict__ W,
               const float* __restrict__ bias, float* __restrict__ Cmat,
               int M, int N, int K) {
    extern __shared__ uint32_t gsm[];

    const int tid  = threadIdx.x;
    const int lane = tid & 31;
    const int wid  = tid >> 5;
    const int g    = lane >> 2;
    const int q    = lane & 3;
    const int wm   = wid >> 1;    // 0..1
    const int wn   = wid & 1;     // 0..1

    const int m0 = blockIdx.y * 128;
    const int n0 = blockIdx.x * 128;
    const float* Abase = A + (size_t)m0 * K;
    const float* Wbase = W + (size_t)n0 * K;
    const int niter = K >> 5;   // K/32

    float acc[4][8][4];
    #pragma unroll
    for (int mi = 0; mi < 4; mi++)
        #pragma unroll
        for (int ni = 0; ni < 8; ni++)
            #pragma unroll
            for (int r = 0; r < 4; r++) acc[mi][ni][r] = 0.0f;

    auto issueTile = [&](int t) {
        uint32_t sb = (uint32_t)__cvta_generic_to_shared(
            gsm + (t % GSTAGES) * GSTAGEW);
        #pragma unroll
        for (int j = 0; j < 8; j++) {
            const int c   = tid + j * 128;     // 0..1023
            const int row = c >> 3;
            const int kc  = (c & 7) << 2;
            cpa16(sb + (row * GPAD + kc) * 4,
                  Abase + (size_t)row * K + t * 32 + kc);
            cpa16(sb + (GTILEW + row * GPAD + kc) * 4,
                  Wbase + (size_t)row * K + t * 32 + kc);
        }
    };

    auto ldfr = [&](uint32_t (&af)[4][4], uint32_t (&bf)[8][2],
                    const uint32_t* sa, const uint32_t* sw, int ks) {
        #pragma unroll
        for (int mi = 0; mi < 4; mi++) {
            const int m = wm * 64 + mi * 16;
            af[mi][0] = sa[(m + g) * GPAD + ks + q];
            af[mi][1] = sa[(m + g + 8) * GPAD + ks + q];
            af[mi][2] = sa[(m + g) * GPAD + ks + q + 4];
            af[mi][3] = sa[(m + g + 8) * GPAD + ks + q + 4];
        }
        #pragma unroll
        for (int ni = 0; ni < 8; ni++) {
            const int n = wn * 64 + ni * 8;
            bf[ni][0] = sw[(n + g) * GPAD + ks + q];
            bf[ni][1] = sw[(n + g) * GPAD + ks + q + 4];
        }
    };
    auto mmas = [&](uint32_t (&af)[4][4], uint32_t (&bf)[8][2]) {
        #pragma unroll
        for (int mi = 0; mi < 4; mi++)
            #pragma unroll
            for (int ni = 0; ni < 8; ni++)
                mma_tf32(acc[mi][ni], af[mi], bf[ni][0], bf[ni][1]);
    };

    // prologue: tiles 0,1
    #pragma unroll
    for (int p = 0; p < GSTAGES - 1; p++) {
        if (p < niter) issueTile(p);
        cpcommit();
    }

    for (int i = 0; i < niter; i++) {
        cpwait<1>();      // all but newest group done -> tile i resident
        __syncthreads();  // all threads; also orders stage reuse

        const uint32_t* sa = gsm + (i % GSTAGES) * GSTAGEW;
        const uint32_t* sw = sa + GTILEW;

        uint32_t afA[4][4], bfA[8][2], afB[4][4], bfB[8][2];
        ldfr(afA, bfA, sa, sw, 0);
        ldfr(afB, bfB, sa, sw, 8);   mmas(afA, bfA);
        ldfr(afA, bfA, sa, sw, 16);  mmas(afB, bfB);
        ldfr(afB, bfB, sa, sw, 24);  mmas(afA, bfA);
        mmas(afB, bfB);

        if (i + 2 < niter) issueTile(i + 2);   // after compute: single-sync safe
        cpcommit();
    }

    #pragma unroll
    for (int mi = 0; mi < 4; mi++) {
        const int m = m0 + wm * 64 + mi * 16 + g;
        #pragma unroll
        for (int ni = 0; ni < 8; ni++) {
            const int n = n0 + wn * 64 + ni * 8 + 2 * q;
            const float b0 = __ldg(&bias[n]);
            const float b1 = __ldg(&bias[n + 1]);
            float o00 = acc[mi][ni][0] + b0, o01 = acc[mi][ni][1] + b1;
            float o10 = acc[mi][ni][2] + b0, o11 = acc[mi][ni][3] + b1;
            if (EPI_CVT) {
                o00 = __uint_as_float(f2tf32(o00));
                o01 = __uint_as_float(f2tf32(o01));
                o10 = __uint_as_float(f2tf32(o10));
                o11 = __uint_as_float(f2tf32(o11));
            }
            *reinterpret_cast<float2*>(&Cmat[(size_t)m * N + n]) =
                make_float2(o00, o01);
            *reinterpret_cast<float2*>(&Cmat[(size_t)(m + 8) * N + n]) =
                make_float2(o10, o11);
        }
    }
}

// ---------------------------------------------------------------------------
// Flash attention, tf32 mma. 128 threads, 4 warps x 32 q-rows (mi=0,1).
// K/V fragment loads shared across both m-tiles. Heavy q-blocks first.
// TWO barriers per K-tile (R10-proven): issueKV(kb+1) precedes the mid-iter
// sync, so the trailing sync is REQUIRED with a 2-stage ring.
// sQ [128][68] raw fp32 (reused as tf32 sP); sK,sV [64][72], 2 stages.
// ---------------------------------------------------------------------------
#define QROWS 128
#define QP_ST 68
#define KV_ST 72
#define QW  (QROWS * QP_ST)     // 8704 words
#define KVW (64 * KV_ST)        // 4608 words
#define ASTW (2 * KVW)          // 9216 words / stage
#define ATT_BYTES ((QW + 2 * ASTW) * 4)   // 108544

__global__ __launch_bounds__(128)
void attn_tc_kernel(const float* __restrict__ kqv, float* __restrict__ y) {
    extern __shared__ uint32_t smem[];
    uint32_t* sQ = smem;

    const int qb  = gridDim.x - 1 - blockIdx.x;   // heavy blocks first
    const int h   = blockIdx.y;
    const int b   = blockIdx.z;
    const int tid = threadIdx.x;
    const int w   = tid >> 5;
    const int lane = tid & 31;
    const int g   = lane >> 2;
    const int q   = lane & 3;
    const int q0  = qb * QROWS;
    const int mrow = 32 * w;          // 32 q-rows per warp
    const float scale = 0.125f;

    const size_t tokStride = (size_t)NH * 3 * HD;
    const size_t headOff   = (size_t)h * 3 * HD;

    auto issueKV = [&](int kb) {
        const int k0 = kb * 64;
        uint32_t base = (uint32_t)__cvta_generic_to_shared(
            smem + QW + (kb & 1) * ASTW);
        #pragma unroll
        for (int j = 0; j < 8; j++) {
            const int c   = tid + j * 128;
            const int row = c >> 4;
            const int c4  = (c & 15) << 2;
            const float* gk =
                &kqv[((size_t)(b * TT + k0 + row)) * tokStride + headOff + c4];
            cpa16(base + (row * KV_ST + c4) * 4, gk);                 // K
            cpa16(base + (KVW + row * KV_ST + c4) * 4, gk + 2 * HD);  // V
        }
    };

    issueKV(0);
    cpcommit();

    // load Q tile (raw tf32-rounded fp32)
    for (int idx = tid; idx < QROWS * 16; idx += 128) {
        const int row = idx >> 4;
        const int c4  = (idx & 15) << 2;
        uint4 v = *reinterpret_cast<const uint4*>(
            &kqv[((size_t)(b * TT + q0 + row)) * tokStride + headOff + HD + c4]);
        uint32_t* dst = &sQ[row * QP_ST + c4];
        dst[0] = v.x; dst[1] = v.y; dst[2] = v.z; dst[3] = v.w;
    }
    __syncthreads();

    // hoist Q fragments for both m-tiles
    uint32_t qf[2][8][4];
    #pragma unroll
    for (int mi = 0; mi < 2; mi++) {
        const int mr = mrow + mi * 16;
        #pragma unroll
        for (int ks = 0; ks < 8; ks++) {
            qf[mi][ks][0] = sQ[(mr + g) * QP_ST + ks * 8 + q];
            qf[mi][ks][1] = sQ[(mr + g + 8) * QP_ST + ks * 8 + q];
            qf[mi][ks][2] = sQ[(mr + g) * QP_ST + ks * 8 + q + 4];
            qf[mi][ks][3] = sQ[(mr + g + 8) * QP_ST + ks * 8 + q + 4];
        }
    }

    float oacc[2][8][4];
    #pragma unroll
    for (int mi = 0; mi < 2; mi++)
        #pragma unroll
        for (int ni = 0; ni < 8; ni++)
            #pragma unroll
            for (int r = 0; r < 4; r++) oacc[mi][ni][r] = 0.0f;
    float m_i[2][2], l_i[2][2];
    #pragma unroll
    for (int mi = 0; mi < 2; mi++) {
        m_i[mi][0] = -1e30f; m_i[mi][1] = -1e30f;
        l_i[mi][0] = 0.0f;   l_i[mi][1] = 0.0f;
    }

    const int nkb = 2 * (qb + 1);   // 64-key tiles covering keys <= q0+127

    for (int kb = 0; kb < nkb; kb++) {
        const int k0 = kb * 64;
        if (kb + 1 < nkb) issueKV(kb + 1);
        cpcommit();
        cpwait<1>();
        __syncthreads();    // tile kb visible to all threads

        const uint32_t* sK = smem + QW + (kb & 1) * ASTW;
        const uint32_t* sV = sK + KVW;

        // ---- S = Q K^T (K frags shared across both m-tiles) ----
        float sa[2][8][4];
        #pragma unroll
        for (int mi = 0; mi < 2; mi++)
            #pragma unroll
            for (int ni = 0; ni < 8; ni++)
                #pragma unroll
                for (int r = 0; r < 4; r++) sa[mi][ni][r] = 0.0f;

        #pragma unroll
        for (int ks = 0; ks < 8; ks++) {
            #pragma unroll
            for (int ni = 0; ni < 8; ni++) {
                uint32_t b0 = sK[(ni * 8 + g) * KV_ST + ks * 8 + q];
                uint32_t b1 = sK[(ni * 8 + g) * KV_ST + ks * 8 + q + 4];
                mma_tf32(sa[0][ni], qf[0][ks], b0, b1);
                mma_tf32(sa[1][ni], qf[1][ks], b0, b1);
            }
        }

        // ---- scale + causal mask + online softmax per m-tile ----
        const bool diag = (kb >= 2 * qb);
        #pragma unroll
        for (int mi = 0; mi < 2; mi++) {
            const int qr0 = q0 + mrow + mi * 16 + g;
            const int qr1 = qr0 + 8;
            #pragma unroll
            for (int ni = 0; ni < 8; ni++) {
                const int key = k0 + ni * 8 + 2 * q;
                sa[mi][ni][0] = (diag && key     > qr0) ? -1e30f : sa[mi][ni][0] * scale;
                sa[mi][ni][1] = (diag && key + 1 > qr0) ? -1e30f : sa[mi][ni][1] * scale;
                sa[mi][ni][2] = (diag && key     > qr1) ? -1e30f : sa[mi][ni][2] * scale;
                sa[mi][ni][3] = (diag && key + 1 > qr1) ? -1e30f : sa[mi][ni][3] * scale;
            }

            float mx0 = -1e30f, mx1 = -1e30f;
            #pragma unroll
            for (int ni = 0; ni < 8; ni++) {
                mx0 = fmaxf(mx0, fmaxf(sa[mi][ni][0], sa[mi][ni][1]));
                mx1 = fmaxf(mx1, fmaxf(sa[mi][ni][2], sa[mi][ni][3]));
            }
            mx0 = fmaxf(mx0, __shfl_xor_sync(0xffffffffu, mx0, 1));
            mx0 = fmaxf(mx0, __shfl_xor_sync(0xffffffffu, mx0, 2));
            mx1 = fmaxf(mx1, __shfl_xor_sync(0xffffffffu, mx1, 1));
            mx1 = fmaxf(mx1, __shfl_xor_sync(0xffffffffu, mx1, 2));
            const float mn0 = fmaxf(m_i[mi][0], mx0);
            const float mn1 = fmaxf(m_i[mi][1], mx1);
            const float al0 = __expf(m_i[mi][0] - mn0);
            const float al1 = __expf(m_i[mi][1] - mn1);
            float rs0 = 0.0f, rs1 = 0.0f;
            #pragma unroll
            for (int ni = 0; ni < 8; ni++) {
                sa[mi][ni][0] = __expf(sa[mi][ni][0] - mn0);
                sa[mi][ni][1] = __expf(sa[mi][ni][1] - mn0);
                sa[mi][ni][2] = __expf(sa[mi][ni][2] - mn1);
                sa[mi][ni][3] = __expf(sa[mi][ni][3] - mn1);
                rs0 += sa[mi][ni][0] + sa[mi][ni][1];
                rs1 += sa[mi][ni][2] + sa[mi][ni][3];
            }
            rs0 += __shfl_xor_sync(0xffffffffu, rs0, 1);
            rs0 += __shfl_xor_sync(0xffffffffu, rs0, 2);
            rs1 += __shfl_xor_sync(0xffffffffu, rs1, 1);
            rs1 += __shfl_xor_sync(0xffffffffu, rs1, 2);
            l_i[mi][0] = l_i[mi][0] * al0 + rs0;
            l_i[mi][1] = l_i[mi][1] * al1 + rs1;
            m_i[mi][0] = mn0; m_i[mi][1] = mn1;
            #pragma unroll
            for (int ni = 0; ni < 8; ni++) {
                oacc[mi][ni][0] *= al0; oacc[mi][ni][1] *= al0;
                oacc[mi][ni][2] *= al1; oacc[mi][ni][3] *= al1;
            }
        }

        // ---- write P (tf32) into sP (= sQ), warp-private rows ----
        uint32_t* sP = sQ;
        #pragma unroll
        for (int mi = 0; mi < 2; mi++) {
            const int mr = mrow + mi * 16;
            #pragma unroll
            for (int ni = 0; ni < 8; ni++) {
                const int c = ni * 8 + 2 * q;
                sP[(mr + g) * QP_ST + c]         = f2tf32(sa[mi][ni][0]);
                sP[(mr + g) * QP_ST + c + 1]     = f2tf32(sa[mi][ni][1]);
                sP[(mr + g + 8) * QP_ST + c]     = f2tf32(sa[mi][ni][2]);
                sP[(mr + g + 8) * QP_ST + c + 1] = f2tf32(sa[mi][ni][3]);
            }
        }
        __syncwarp();

        // ---- O += P @ V (V frags shared across both m-tiles) ----
        #pragma unroll
        for (int ks = 0; ks < 8; ks++) {
            uint32_t pa[2][4];
            #pragma unroll
            for (int mi = 0; mi < 2; mi++) {
                const int mr = mrow + mi * 16;
                pa[mi][0] = sP[(mr + g) * QP_ST + ks * 8 + q];
                pa[mi][1] = sP[(mr + g + 8) * QP_ST + ks * 8 + q];
                pa[mi][2] = sP[(mr + g) * QP_ST + ks * 8 + q + 4];
                pa[mi][3] = sP[(mr + g + 8) * QP_ST + ks * 8 + q + 4];
            }
            #pragma unroll
            for (int ni = 0; ni < 8; ni++) {
                uint32_t b0 = sV[(ks * 8 + q) * KV_ST + ni * 8 + g];
                uint32_t b1 = sV[(ks * 8 + q + 4) * KV_ST + ni * 8 + g];
                mma_tf32(oacc[0][ni], pa[0], b0, b1);
                mma_tf32(oacc[1][ni], pa[1], b0, b1);
            }
        }
        __syncthreads();   // REQUIRED: stage (kb+1)&1 written at next iter top
    }

    // ---- normalize + write y ----
    #pragma unroll
    for (int mi = 0; mi < 2; mi++) {
        const float il0 = 1.0f / l_i[mi][0];
        const float il1 = 1.0f / l_i[mi][1];
        const int t0 = q0 + mrow + mi * 16 + g;
        const int t1 = t0 + 8;
        #pragma unroll
        for (int ni = 0; ni < 8; ni++) {
            const int col = h * HD + ni * 8 + 2 * q;
            uint2 v0 = make_uint2(f2tf32(oacc[mi][ni][0] * il0),
                                  f2tf32(oacc[mi][ni][1] * il0));
            uint2 v1 = make_uint2(f2tf32(oacc[mi][ni][2] * il1),
                                  f2tf32(oacc[mi][ni][3] * il1));
            *reinterpret_cast<uint2*>(&y[(size_t)(b * TT + t0) * CC + col]) = v0;
            *reinterpret_cast<uint2*>(&y[(size_t)(b * TT + t1) * CC + col]) = v1;
        }
    }
}

// ---------------------------------------------------------------------------
extern "C" void kernel_launch(void* const* d_in, const int* in_sizes, int n_in,
                              void* d_out, int out_size) {
    (void)in_sizes; (void)n_in; (void)out_size;
    const float* x      = (const float*)d_in[0];
    const float* W_kqv  = (const float*)d_in[1];
    const float* b_kqv  = (const float*)d_in[2];
    const float* W_proj = (const float*)d_in[3];
    const float* b_proj = (const float*)d_in[4];
    float* out = (float*)d_out;

    float *kqv = nullptr, *y = nullptr, *xtf = nullptr, *wk = nullptr, *wp = nullptr;
    cudaGetSymbolAddress((void**)&kqv, g_kqv);
    cudaGetSymbolAddress((void**)&y, g_y);
    cudaGetSymbolAddress((void**)&xtf, g_xtf);
    cudaGetSymbolAddress((void**)&wk, g_wk);
    cudaGetSymbolAddress((void**)&wp, g_wp);

    cudaFuncSetAttribute(gemm_tf32<true>, cudaFuncAttributeMaxDynamicSharedMemorySize,
                         GSMEM_BYTES);
    cudaFuncSetAttribute(gemm_tf32<false>, cudaFuncAttributeMaxDynamicSharedMemorySize,
                         GSMEM_BYTES);
    cudaFuncSetAttribute(attn_tc_kernel, cudaFuncAttributeMaxDynamicSharedMemorySize,
                         ATT_BYTES);

    // 0) pre-round inputs to tf32
    {
        int n4x = (BT * CC) / 4;
        cvt_tf32_kernel<<<(n4x + 255) / 256, 256>>>(
            (const float4*)x, (uint4*)xtf, n4x);
        int n4k = (KQV3 * CC) / 4;
        cvt_tf32_kernel<<<(n4k + 255) / 256, 256>>>(
            (const float4*)W_kqv, (uint4*)wk, n4k);
        int n4p = (CC * CC) / 4;
        cvt_tf32_kernel<<<(n4p + 255) / 256, 256>>>(
            (const float4*)W_proj, (uint4*)wp, n4p);
    }
    // 1) kqv = x @ W_kqv^T + b_kqv  (epilogue tf32-rounds)
    {
        dim3 grid(KQV3 / 128, BT / 128);
        gemm_tf32<true><<<grid, 128, GSMEM_BYTES>>>(xtf, wk, b_kqv, kqv,
                                                    BT, KQV3, CC);
    }
    // 2) flash attention -> y (tf32-rounded)
    {
        dim3 grid(TT / QROWS, NH, BB);
        attn_tc_kernel<<<grid, 128, ATT_BYTES>>>(kqv, y);
    }
    // 3) out = y @ W_proj^T + b_proj (plain fp32 epilogue)
    {
        dim3 grid(CC / 128, BT / 128);
        gemm_tf32<false><<<grid, 128, GSMEM_BYTES>>>(y, wp, b_proj, out,
                                                     BT, CC, CC);
    }
}